// round 1
// baseline (speedup 1.0000x reference)
#include <cuda_runtime.h>
#include <math.h>

// Problem constants (fixed in reference)
#define D    80
#define E    8
#define HID  320
#define NL   4

// Tiling
#define TB   64     // tokens per FFN block
#define HT   64     // hid tile
#define MAXT 131072 // max tokens supported (actual: 24000)

// Scratch (no cudaMalloc allowed)
__device__ float g_bufA[MAXT * D];
__device__ float g_bufB[MAXT * D];
__device__ int   g_cnt[E];
__device__ int   g_tok[E * MAXT];
__device__ float g_wt [E * MAXT];

// ---------------------------------------------------------------------------
// Router: per-token logits = x·Wg[l] + bg[l]; top-2 (jax top_k tie semantics:
// strict > keeps the lower index). Append (token, raw logit value) to the two
// chosen experts' lists.
// ---------------------------------------------------------------------------
__global__ void router_kernel(const float* __restrict__ x,
                              const float* __restrict__ Wg,   // [D,E] for this layer
                              const float* __restrict__ bg,   // [E]
                              int T) {
    __shared__ float wg[D * E];
    __shared__ float bgs[E];
    for (int i = threadIdx.x; i < D * E; i += blockDim.x) wg[i] = Wg[i];
    if (threadIdx.x < E) bgs[threadIdx.x] = bg[threadIdx.x];
    __syncthreads();

    int t = blockIdx.x * blockDim.x + threadIdx.x;
    if (t >= T) return;

    float acc[E];
    #pragma unroll
    for (int e = 0; e < E; e++) acc[e] = bgs[e];

    const float* xr = x + (size_t)t * D;
    #pragma unroll 4
    for (int k = 0; k < D; k++) {
        float xv = xr[k];
        #pragma unroll
        for (int e = 0; e < E; e++) acc[e] = fmaf(xv, wg[k * E + e], acc[e]);
    }

    float v0 = -INFINITY, v1 = -INFINITY;
    int   i0 = 0, i1 = 0;
    #pragma unroll
    for (int e = 0; e < E; e++) {
        float v = acc[e];
        if (v > v0)      { v1 = v0; i1 = i0; v0 = v; i0 = e; }
        else if (v > v1) { v1 = v;  i1 = e; }
    }

    int p0 = atomicAdd(&g_cnt[i0], 1);
    g_tok[i0 * MAXT + p0] = t;  g_wt[i0 * MAXT + p0] = v0;
    int p1 = atomicAdd(&g_cnt[i1], 1);
    g_tok[i1 * MAXT + p1] = t;  g_wt[i1 * MAXT + p1] = v1;
}

// ---------------------------------------------------------------------------
// Grouped FFN: block = (chunk, expert). Gathers up to TB tokens of expert e,
// computes  y = relu(X W1[e] + b1[e]) W2[e] + b2[e]  with HID tiled by HT,
// then atomically scatters  w * y  into the layer output.
// ---------------------------------------------------------------------------
__global__ void __launch_bounds__(256)
ffn_kernel(const float* __restrict__ in,  float* __restrict__ out,
           const float* __restrict__ W1,  const float* __restrict__ b1,
           const float* __restrict__ W2,  const float* __restrict__ b2) {
    int e = blockIdx.y;
    int n = g_cnt[e];
    int start = blockIdx.x * TB;
    if (start >= n) return;

    __shared__ float xs[TB][D];        // gathered activations (20 KB)
    __shared__ float hts[TB][HT + 4];  // hid tile, padded rows (17.4 KB)
    __shared__ int   stok[TB];
    __shared__ float swt[TB];

    int tid = threadIdx.x;
    if (tid < TB) {
        int p = start + tid;
        if (p < n) { stok[tid] = g_tok[e * MAXT + p]; swt[tid] = g_wt[e * MAXT + p]; }
        else       { stok[tid] = -1;                  swt[tid] = 0.f; }
    }
    __syncthreads();

    // gather X rows (rows are 320B contiguous -> coalesced within rows)
    for (int i = tid; i < TB * D; i += 256) {
        int r = i / D, c = i - r * D;
        int tk = stok[r];
        xs[r][c] = (tk >= 0) ? in[(size_t)tk * D + c] : 0.f;
    }

    // stage-2 mapping: thread = (tt, dt); tokens tt+16i (i<4), dims dt+16m (m<5)
    int dt = tid & 15;
    int tt = tid >> 4;
    // stage-1 mapping: thread = (wrp, lane); tokens wrp+8i (i<8), hid lane(+32)
    int lane = tid & 31;
    int wrp  = tid >> 5;

    float yacc[4][5];
    {
        float b2v[5];
        #pragma unroll
        for (int m = 0; m < 5; m++) b2v[m] = b2[e * D + dt + 16 * m];
        #pragma unroll
        for (int i = 0; i < 4; i++)
            #pragma unroll
            for (int m = 0; m < 5; m++) yacc[i][m] = b2v[m];
    }

    const float* W1e = W1 + (size_t)e * D * HID;
    const float* W2e = W2 + (size_t)e * HID * D;
    __syncthreads();

    for (int kt = 0; kt < HID; kt += HT) {
        // ---- stage 1: hts = relu(X * W1[:, kt:kt+HT] + b1) ----
        float hacc[8][2];
        {
            float b10 = b1[e * HID + kt + lane];
            float b11 = b1[e * HID + kt + lane + 32];
            #pragma unroll
            for (int i = 0; i < 8; i++) { hacc[i][0] = b10; hacc[i][1] = b11; }
        }
        #pragma unroll 2
        for (int k = 0; k < D; k += 4) {
            float xv[8][4];
            #pragma unroll
            for (int i = 0; i < 8; i++) {
                float4 v = *(const float4*)&xs[wrp + 8 * i][k];
                xv[i][0] = v.x; xv[i][1] = v.y; xv[i][2] = v.z; xv[i][3] = v.w;
            }
            #pragma unroll
            for (int kk = 0; kk < 4; kk++) {
                float w0 = W1e[(size_t)(k + kk) * HID + kt + lane];
                float w1 = W1e[(size_t)(k + kk) * HID + kt + lane + 32];
                #pragma unroll
                for (int i = 0; i < 8; i++) {
                    hacc[i][0] = fmaf(xv[i][kk], w0, hacc[i][0]);
                    hacc[i][1] = fmaf(xv[i][kk], w1, hacc[i][1]);
                }
            }
        }
        #pragma unroll
        for (int i = 0; i < 8; i++) {
            hts[wrp + 8 * i][lane]      = fmaxf(hacc[i][0], 0.f);
            hts[wrp + 8 * i][lane + 32] = fmaxf(hacc[i][1], 0.f);
        }
        __syncthreads();

        // ---- stage 2: Y += hts * W2[kt:kt+HT, :] ----
        #pragma unroll 4
        for (int h = 0; h < HT; h++) {
            const float* w2r = W2e + (size_t)(kt + h) * D;
            float w2v[5];
            #pragma unroll
            for (int m = 0; m < 5; m++) w2v[m] = w2r[dt + 16 * m];
            #pragma unroll
            for (int i = 0; i < 4; i++) {
                float xh = hts[tt + 16 * i][h];
                #pragma unroll
                for (int m = 0; m < 5; m++)
                    yacc[i][m] = fmaf(xh, w2v[m], yacc[i][m]);
            }
        }
        __syncthreads();
    }

    // ---- scatter: out[tok] += w * y  (exactly 2 contributions/token -> deterministic)
    #pragma unroll
    for (int i = 0; i < 4; i++) {
        int r = tt + 16 * i;
        int tk = stok[r];
        if (tk < 0) continue;
        float w = swt[r];
        #pragma unroll
        for (int m = 0; m < 5; m++)
            atomicAdd(&out[(size_t)tk * D + dt + 16 * m], w * yacc[i][m]);
    }
}

// ---------------------------------------------------------------------------
extern "C" void kernel_launch(void* const* d_in, const int* in_sizes, int n_in,
                              void* d_out, int out_size) {
    const float* x  = (const float*)d_in[0];
    const float* Wg = (const float*)d_in[1];
    const float* bg = (const float*)d_in[2];
    const float* W1 = (const float*)d_in[3];
    const float* b1 = (const float*)d_in[4];
    const float* W2 = (const float*)d_in[5];
    const float* b2 = (const float*)d_in[6];
    float* out = (float*)d_out;

    int T = in_sizes[0] / D;

    void *cntp, *bufAp, *bufBp;
    cudaGetSymbolAddress(&cntp,  g_cnt);
    cudaGetSymbolAddress(&bufAp, g_bufA);
    cudaGetSymbolAddress(&bufBp, g_bufB);
    float* bufA = (float*)bufAp;
    float* bufB = (float*)bufBp;

    int  rb     = (T + 255) / 256;
    int  chunks = (T + TB - 1) / TB;
    dim3 fgrid(chunks, E);

    const float* lin = x;
    for (int l = 0; l < NL; l++) {
        float* lout = (l == NL - 1) ? out : ((l & 1) ? bufB : bufA);
        cudaMemsetAsync(cntp, 0, sizeof(int) * E);
        cudaMemsetAsync(lout, 0, (size_t)T * D * sizeof(float));
        router_kernel<<<rb, 256>>>(lin, Wg + l * D * E, bg + l * E, T);
        ffn_kernel<<<fgrid, 256>>>(lin, lout, W1, b1, W2, b2);
        lin = lout;
    }
}

// round 2
// speedup vs baseline: 1.0368x; 1.0368x over previous
#include <cuda_runtime.h>
#include <math.h>

// Problem constants
#define D    80
#define E    8
#define HID  320
#define NL   4

// Tiling
#define TB   64            // tokens per FFN block
#define HT   32            // hid tile
#define NKT  (HID / HT)    // 10
#define MAXT 131072

typedef unsigned long long u64;

// Scratch (no cudaMalloc allowed)
__device__ float g_bufA[MAXT * D];
__device__ float g_bufB[MAXT * D];
__device__ int   g_cnt[E];
__device__ int   g_tok[E * MAXT];
__device__ float g_wt [E * MAXT];

// ---- packed f32x2 helpers (Blackwell dual-FMA; PTX-only, ptxas won't emit) ----
__device__ __forceinline__ u64 pack2(float lo, float hi) {
    u64 r; asm("mov.b64 %0, {%1, %2};" : "=l"(r) : "f"(lo), "f"(hi)); return r;
}
__device__ __forceinline__ u64 ffma2(u64 a, u64 b, u64 c) {
    u64 d; asm("fma.rn.f32x2 %0, %1, %2, %3;" : "=l"(d) : "l"(a), "l"(b), "l"(c)); return d;
}
__device__ __forceinline__ float2 unpack2(u64 v) {
    float2 f; asm("mov.b64 {%0, %1}, %2;" : "=f"(f.x), "=f"(f.y) : "l"(v)); return f;
}

// ---------------------------------------------------------------------------
// Router: logits = x·Wg[l] + bg[l]; top-2 with jax top_k tie semantics
// (strict > keeps the lower index). Raw logit values are the combine weights.
// ---------------------------------------------------------------------------
__global__ void router_kernel(const float* __restrict__ x,
                              const float* __restrict__ Wg,   // [D,E]
                              const float* __restrict__ bg,   // [E]
                              int T) {
    __shared__ float wg[D * E];
    __shared__ float bgs[E];
    for (int i = threadIdx.x; i < D * E; i += blockDim.x) wg[i] = Wg[i];
    if (threadIdx.x < E) bgs[threadIdx.x] = bg[threadIdx.x];
    __syncthreads();

    int t = blockIdx.x * blockDim.x + threadIdx.x;
    if (t >= T) return;

    float acc[E];
    #pragma unroll
    for (int e = 0; e < E; e++) acc[e] = bgs[e];

    const float* xr = x + (size_t)t * D;
    #pragma unroll 4
    for (int k = 0; k < D; k++) {
        float xv = xr[k];
        #pragma unroll
        for (int e = 0; e < E; e++) acc[e] = fmaf(xv, wg[k * E + e], acc[e]);
    }

    float v0 = -INFINITY, v1 = -INFINITY;
    int   i0 = 0, i1 = 0;
    #pragma unroll
    for (int e = 0; e < E; e++) {
        float v = acc[e];
        if (v > v0)      { v1 = v0; i1 = i0; v0 = v; i0 = e; }
        else if (v > v1) { v1 = v;  i1 = e; }
    }

    int p0 = atomicAdd(&g_cnt[i0], 1);
    g_tok[i0 * MAXT + p0] = t;  g_wt[i0 * MAXT + p0] = v0;
    int p1 = atomicAdd(&g_cnt[i1], 1);
    g_tok[i1 * MAXT + p1] = t;  g_wt[i1 * MAXT + p1] = v1;
}

// ---------------------------------------------------------------------------
// Grouped FFN with packed f32x2 math.
//   smem: xs  [D][64]    X transposed (token-contiguous -> vector token-pairs)
//         hts [HT][66]   hidden tile, transposed, padded (STS 2-way max)
//         w2t [HT][D]    W2 tile (contiguous copy)
//   W1 read straight from global: 32 consecutive floats/warp (L1/L2-hot).
// ---------------------------------------------------------------------------
__global__ void __launch_bounds__(256, 4)
ffn_kernel(const float* __restrict__ in,  float* __restrict__ out,
           const float* __restrict__ W1,  const float* __restrict__ b1,
           const float* __restrict__ W2,  const float* __restrict__ b2) {
    int e = blockIdx.y;
    int n = g_cnt[e];
    int start = blockIdx.x * TB;
    if (start >= n) return;

    __shared__ float xs [D * TB];        // [k*64 + t]      20.0 KB
    __shared__ float hts[HT * 66];       // [h*66 + t]       8.25 KB
    __shared__ float w2t[HT * D];        // [h*80 + d]      10.0 KB
    __shared__ int   stok[TB];
    __shared__ float swt[TB];

    int tid = threadIdx.x;
    if (tid < TB) {
        int p = start + tid;
        if (p < n) { stok[tid] = g_tok[e * MAXT + p]; swt[tid] = g_wt[e * MAXT + p]; }
        else       { stok[tid] = -1;                  swt[tid] = 0.f; }
    }
    __syncthreads();

    // ---- gather X, transposed: 4 threads per token, 5 float4 each ----
    {
        int r = tid >> 2, sub = tid & 3;
        int tk = stok[r];
        const float* xr = in + (size_t)(tk < 0 ? 0 : tk) * D;
        #pragma unroll
        for (int j = 0; j < 5; j++) {
            int c = sub * 4 + j * 16;
            float4 v;
            if (tk >= 0) v = *(const float4*)&xr[c];
            else         v = make_float4(0.f, 0.f, 0.f, 0.f);
            xs[(c + 0) * TB + r] = v.x;
            xs[(c + 1) * TB + r] = v.y;
            xs[(c + 2) * TB + r] = v.z;
            xs[(c + 3) * TB + r] = v.w;
        }
    }

    const float* W1e = W1 + (size_t)e * D * HID;
    const float* W2e = W2 + (size_t)e * HID * D;

    // stage-1 mapping: warp wrp owns tokens [8wrp, 8wrp+8) (4 packed pairs),
    //                  lane = hid index within tile
    int lane = tid & 31;
    int wrp  = tid >> 5;
    // stage-2 mapping: tg owns tokens [4tg, 4tg+4) (2 packed pairs),
    //                  dims dg + 16m, m<5
    int dg = tid & 15;
    int tg = tid >> 4;

    // yacc packed across tokens: yacc[pair][m]; init with b2 (added once)
    u64 yacc[2][5];
    #pragma unroll
    for (int m = 0; m < 5; m++) {
        float bv = b2[e * D + dg + 16 * m];
        u64 p = pack2(bv, bv);
        yacc[0][m] = p; yacc[1][m] = p;
    }

    for (int kt = 0; kt < NKT; kt++) {
        __syncthreads();   // prior stage-2 done with hts/w2t; gather done (kt=0)

        // ---- stage W2 tile (contiguous 32x80 floats) ----
        {
            const float* W2c = W2e + (size_t)kt * HT * D;
            #pragma unroll
            for (int i = 0; i < (HT * D / 2) / 256; i++) {
                int f = 2 * (tid + i * 256);
                *(float2*)&w2t[f] = *(const float2*)&W2c[f];
            }
        }

        // ---- stage 1: h = relu(X W1tile + b1), packed over token pairs ----
        {
            float b1v = b1[e * HID + kt * HT + lane];
            u64 hb = pack2(b1v, b1v);
            u64 hacc0 = hb, hacc1 = hb, hacc2 = hb, hacc3 = hb;
            const float* w1p = W1e + kt * HT + lane;   // stride HID per k
            const float* xp  = xs + 8 * wrp;
            #pragma unroll 4
            for (int k = 0; k < D; k++) {
                ulonglong2 xa = *(const ulonglong2*)&xp[k * TB];       // tokens 0-3
                ulonglong2 xb = *(const ulonglong2*)&xp[k * TB + 4];   // tokens 4-7
                float wv = w1p[(size_t)k * HID];
                u64 wp = pack2(wv, wv);
                hacc0 = ffma2(xa.x, wp, hacc0);
                hacc1 = ffma2(xa.y, wp, hacc1);
                hacc2 = ffma2(xb.x, wp, hacc2);
                hacc3 = ffma2(xb.y, wp, hacc3);
            }
            float* hrow = hts + lane * 66 + 8 * wrp;
            float2 v;
            v = unpack2(hacc0); v.x = fmaxf(v.x, 0.f); v.y = fmaxf(v.y, 0.f); *(float2*)&hrow[0] = v;
            v = unpack2(hacc1); v.x = fmaxf(v.x, 0.f); v.y = fmaxf(v.y, 0.f); *(float2*)&hrow[2] = v;
            v = unpack2(hacc2); v.x = fmaxf(v.x, 0.f); v.y = fmaxf(v.y, 0.f); *(float2*)&hrow[4] = v;
            v = unpack2(hacc3); v.x = fmaxf(v.x, 0.f); v.y = fmaxf(v.y, 0.f); *(float2*)&hrow[6] = v;
        }
        __syncthreads();

        // ---- stage 2: Y += H_tile * W2_tile, packed over token pairs ----
        {
            const float* hp = hts + 4 * tg;
            const float* wp2 = w2t + dg;
            #pragma unroll 4
            for (int h = 0; h < HT; h++) {
                u64 xp0 = *(const u64*)&hp[h * 66];       // tokens (4tg, 4tg+1)
                u64 xp1 = *(const u64*)&hp[h * 66 + 2];   // tokens (4tg+2, 4tg+3)
                const float* wr = wp2 + h * D;
                #pragma unroll
                for (int m = 0; m < 5; m++) {
                    float w = wr[16 * m];
                    u64 wpk = pack2(w, w);
                    yacc[0][m] = ffma2(xp0, wpk, yacc[0][m]);
                    yacc[1][m] = ffma2(xp1, wpk, yacc[1][m]);
                }
            }
        }
    }

    // ---- scatter: out[tok] += w * y (2 contributions/token -> deterministic)
    #pragma unroll
    for (int pr = 0; pr < 2; pr++) {
        int r0 = 4 * tg + 2 * pr;
        int tk0 = stok[r0], tk1 = stok[r0 + 1];
        float w0 = swt[r0], w1v = swt[r0 + 1];
        #pragma unroll
        for (int m = 0; m < 5; m++) {
            float2 v = unpack2(yacc[pr][m]);
            if (tk0 >= 0) atomicAdd(&out[(size_t)tk0 * D + dg + 16 * m], w0  * v.x);
            if (tk1 >= 0) atomicAdd(&out[(size_t)tk1 * D + dg + 16 * m], w1v * v.y);
        }
    }
}

// ---------------------------------------------------------------------------
extern "C" void kernel_launch(void* const* d_in, const int* in_sizes, int n_in,
                              void* d_out, int out_size) {
    const float* x  = (const float*)d_in[0];
    const float* Wg = (const float*)d_in[1];
    const float* bg = (const float*)d_in[2];
    const float* W1 = (const float*)d_in[3];
    const float* b1 = (const float*)d_in[4];
    const float* W2 = (const float*)d_in[5];
    const float* b2 = (const float*)d_in[6];
    float* out = (float*)d_out;

    int T = in_sizes[0] / D;

    void *cntp, *bufAp, *bufBp;
    cudaGetSymbolAddress(&cntp,  g_cnt);
    cudaGetSymbolAddress(&bufAp, g_bufA);
    cudaGetSymbolAddress(&bufBp, g_bufB);
    float* bufA = (float*)bufAp;
    float* bufB = (float*)bufBp;

    int  rb     = (T + 255) / 256;
    int  chunks = (T + TB - 1) / TB;
    dim3 fgrid(chunks, E);

    const float* lin = x;
    for (int l = 0; l < NL; l++) {
        float* lout = (l == NL - 1) ? out : ((l & 1) ? bufB : bufA);
        cudaMemsetAsync(cntp, 0, sizeof(int) * E);
        cudaMemsetAsync(lout, 0, (size_t)T * D * sizeof(float));
        router_kernel<<<rb, 256>>>(lin, Wg + l * D * E, bg + l * E, T);
        ffn_kernel<<<fgrid, 256>>>(lin, lout, W1, b1, W2, b2);
        lin = lout;
    }
}

// round 4
// speedup vs baseline: 2.2919x; 2.2107x over previous
#include <cuda_runtime.h>
#include <cuda_bf16.h>
#include <math.h>
#include <stdint.h>

// Problem constants
#define D    80
#define E    8
#define HID  320
#define NL   4
#define TBK  64            // tokens per ffn block
#define NCK  5             // HID chunks of 64
#define MAXT 131072

// smem row strides (elements) — odd multiples of 8 -> conflict-free ldmatrix
#define XS   88
#define W1S  72
#define HS   72
#define W2S  88

// smem layout (bytes)
#define SM_STOK 0
#define SM_SWT  256
#define SM_SB1  512
#define SM_SB2  768
#define SM_XHI  1280
#define SM_XLO  (SM_XHI  + TBK * XS * 2)     // 12544
#define SM_W1HI (SM_XLO  + TBK * XS * 2)     // 23808
#define SM_W1LO (SM_W1HI + 80 * W1S * 2)     // 35328
#define SM_W2HI (SM_W1LO + 80 * W1S * 2)     // 46848
#define SM_W2LO (SM_W2HI + 64 * W2S * 2)     // 58112
#define SM_HHI  (SM_W2LO + 64 * W2S * 2)     // 69376
#define SM_HLO  (SM_HHI  + TBK * HS * 2)     // 78592
#define SMEM_TOTAL (SM_HLO + TBK * HS * 2)   // 87808

// ---------------------------------------------------------------------------
// Scratch (no cudaMalloc allowed)
// ---------------------------------------------------------------------------
__device__ float g_bufA[MAXT * D];
__device__ float g_bufB[MAXT * D];
__device__ int   g_cnt[E];
__device__ int   g_tok[E * MAXT];
__device__ float g_wt [E * MAXT];
// split-bf16 weights, natural layouts
__device__ __align__(16) unsigned short g_w1h[E * D * HID];   // [e][d][h]
__device__ __align__(16) unsigned short g_w1l[E * D * HID];
__device__ __align__(16) unsigned short g_w2h[E * HID * D];   // [e][h][d]
__device__ __align__(16) unsigned short g_w2l[E * HID * D];

// ---------------------------------------------------------------------------
// PTX helpers (sm_80-era: valid on compute_100 without the 'a' suffix)
// ---------------------------------------------------------------------------
__device__ __forceinline__ uint32_t smem_u32(const void* p) {
    uint32_t a;
    asm("{ .reg .u64 t; cvta.to.shared.u64 t, %1; cvt.u32.u64 %0, t; }" : "=r"(a) : "l"(p));
    return a;
}
__device__ __forceinline__ void ldsm4(uint32_t* r, uint32_t a) {
    asm volatile("ldmatrix.sync.aligned.m8n8.x4.shared.b16 {%0,%1,%2,%3}, [%4];"
        : "=r"(r[0]), "=r"(r[1]), "=r"(r[2]), "=r"(r[3]) : "r"(a));
}
__device__ __forceinline__ void ldsm2t(uint32_t* r, uint32_t a) {
    asm volatile("ldmatrix.sync.aligned.m8n8.x2.trans.shared.b16 {%0,%1}, [%2];"
        : "=r"(r[0]), "=r"(r[1]) : "r"(a));
}
__device__ __forceinline__ void mma_bf16(float* c, const uint32_t* a, const uint32_t* b) {
    asm volatile("mma.sync.aligned.m16n8k16.row.col.f32.bf16.bf16.f32 "
        "{%0,%1,%2,%3}, {%4,%5,%6,%7}, {%8,%9}, {%0,%1,%2,%3};"
        : "+f"(c[0]), "+f"(c[1]), "+f"(c[2]), "+f"(c[3])
        : "r"(a[0]), "r"(a[1]), "r"(a[2]), "r"(a[3]), "r"(b[0]), "r"(b[1]));
}
__device__ __forceinline__ uint32_t pack_bf2(float a, float b) {
    __nv_bfloat162 h = __floats2bfloat162_rn(a, b);
    return *(uint32_t*)&h;
}

// ---------------------------------------------------------------------------
// Weight prep: elementwise split fp32 -> bf16 hi + lo
// ---------------------------------------------------------------------------
__global__ void prep_kernel(const float* __restrict__ W1, const float* __restrict__ W2) {
    int i = blockIdx.x * blockDim.x + threadIdx.x;
    const int N1 = E * D * HID;
    const int N2 = E * HID * D;
    if (i < N1) {
        float v = W1[i];
        __nv_bfloat16 h = __float2bfloat16(v);
        __nv_bfloat16 l = __float2bfloat16(v - __bfloat162float(h));
        g_w1h[i] = *(unsigned short*)&h;
        g_w1l[i] = *(unsigned short*)&l;
    } else if (i < N1 + N2) {
        int j = i - N1;
        float v = W2[j];
        __nv_bfloat16 h = __float2bfloat16(v);
        __nv_bfloat16 l = __float2bfloat16(v - __bfloat162float(h));
        g_w2h[j] = *(unsigned short*)&h;
        g_w2l[j] = *(unsigned short*)&l;
    }
}

// ---------------------------------------------------------------------------
// Router (fp32, exact jax top_k tie semantics; raw logits are weights)
// ---------------------------------------------------------------------------
__global__ void router_kernel(const float* __restrict__ x,
                              const float* __restrict__ Wg,
                              const float* __restrict__ bg, int T) {
    __shared__ float wg[D * E];
    __shared__ float bgs[E];
    for (int i = threadIdx.x; i < D * E; i += blockDim.x) wg[i] = Wg[i];
    if (threadIdx.x < E) bgs[threadIdx.x] = bg[threadIdx.x];
    __syncthreads();
    int t = blockIdx.x * blockDim.x + threadIdx.x;
    if (t >= T) return;
    float acc[E];
    #pragma unroll
    for (int e = 0; e < E; e++) acc[e] = bgs[e];
    const float* xr = x + (size_t)t * D;
    #pragma unroll 4
    for (int k = 0; k < D; k++) {
        float xv = xr[k];
        #pragma unroll
        for (int e = 0; e < E; e++) acc[e] = fmaf(xv, wg[k * E + e], acc[e]);
    }
    float v0 = -INFINITY, v1 = -INFINITY; int i0 = 0, i1 = 0;
    #pragma unroll
    for (int e = 0; e < E; e++) {
        float v = acc[e];
        if (v > v0)      { v1 = v0; i1 = i0; v0 = v; i0 = e; }
        else if (v > v1) { v1 = v;  i1 = e; }
    }
    int p0 = atomicAdd(&g_cnt[i0], 1);
    g_tok[i0 * MAXT + p0] = t;  g_wt[i0 * MAXT + p0] = v0;
    int p1 = atomicAdd(&g_cnt[i1], 1);
    g_tok[i1 * MAXT + p1] = t;  g_wt[i1 * MAXT + p1] = v1;
}

// ---------------------------------------------------------------------------
// FFN: 64 tokens of one expert; split-bf16 tensor-core GEMMs via mma.sync
// ---------------------------------------------------------------------------
__global__ void __launch_bounds__(256, 2)
ffn_kernel(const float* __restrict__ in,  float* __restrict__ out,
           const float* __restrict__ b1,  const float* __restrict__ b2) {
    extern __shared__ char smem[];
    uint32_t sb = smem_u32(smem);
    int tid  = threadIdx.x;
    int lane = tid & 31;
    int wid  = tid >> 5;

    int e = blockIdx.y;
    int n = g_cnt[e];
    int start = blockIdx.x * TBK;
    if (start >= n) return;

    int*   stok = (int*)  (smem + SM_STOK);
    float* swt  = (float*)(smem + SM_SWT);
    float* sb1  = (float*)(smem + SM_SB1);
    float* sb2  = (float*)(smem + SM_SB2);

    if (tid < TBK) {
        int p = start + tid;
        if (p < n) { stok[tid] = g_tok[e * MAXT + p]; swt[tid] = g_wt[e * MAXT + p]; }
        else       { stok[tid] = -1; swt[tid] = 0.f; }
    }
    if (tid < D) sb2[tid] = b2[e * D + tid];
    __syncthreads();

    // ---- gather X, split into bf16 hi/lo smem (2 threads per token) ----
    if (tid < 2 * TBK) {
        int r = tid >> 1, half = tid & 1;
        int tk = stok[r];
        const float* xr = in + (size_t)(tk < 0 ? 0 : tk) * D + half * 40;
        char* dh = smem + SM_XHI + (r * XS + half * 40) * 2;
        char* dl = smem + SM_XLO + (r * XS + half * 40) * 2;
        #pragma unroll
        for (int j = 0; j < 20; j++) {
            float2 v = (tk >= 0) ? *(const float2*)&xr[2 * j] : make_float2(0.f, 0.f);
            __nv_bfloat162 h2 = __floats2bfloat162_rn(v.x, v.y);
            float2 hf = __bfloat1622float2(h2);
            __nv_bfloat162 l2 = __floats2bfloat162_rn(v.x - hf.x, v.y - hf.y);
            *(uint32_t*)(dh + 4 * j) = *(uint32_t*)&h2;
            *(uint32_t*)(dl + 4 * j) = *(uint32_t*)&l2;
        }
    }

    // warp tiling: 4 (M) x 2 (N)
    int warp_m = wid >> 1;
    int warp_n = wid & 1;
    int m_base = warp_m * 16;

    // per-thread ldmatrix base addresses
    uint32_t aX  = sb + SM_XHI + ((m_base + (lane & 15)) * XS + (lane >> 4) * 8) * 2;
    uint32_t bW1 = sb + SM_W1HI + ((lane & 15) * W1S + warp_n * 32) * 2;
    uint32_t aH  = sb + SM_HHI + ((m_base + (lane & 15)) * HS + (lane >> 4) * 8) * 2;
    uint32_t bW2 = sb + SM_W2HI + ((lane & 15) * W2S + warp_n * 40) * 2;
    const int dXlo  = SM_XLO  - SM_XHI;
    const int dW1lo = SM_W1LO - SM_W1HI;
    const int dHlo  = SM_HLO  - SM_HHI;
    const int dW2lo = SM_W2LO - SM_W2HI;

    // GEMM2 accumulators persist over chunks: warp tile 16 x 40 (5 n-atoms)
    float yacc[5][4];
    #pragma unroll
    for (int na = 0; na < 5; na++)
        #pragma unroll
        for (int i = 0; i < 4; i++) yacc[na][i] = 0.f;

    const unsigned short* w1hB = g_w1h + e * D * HID;
    const unsigned short* w1lB = g_w1l + e * D * HID;
    const unsigned short* w2hB = g_w2h + e * HID * D;
    const unsigned short* w2lB = g_w2l + e * HID * D;

    for (int c = 0; c < NCK; c++) {
        __syncthreads();   // prev GEMM2 done with W2/H; X gather done (c=0)

        // ---- stage weight tiles into smem (vectorized, L2-hot) ----
        {
            const unsigned short* s1h = w1hB + c * 64;
            const unsigned short* s1l = w1lB + c * 64;
            #pragma unroll 2
            for (int idx = tid; idx < 640; idx += 256) {
                int row = idx >> 3, v = idx & 7;
                int dsto = (row * W1S + v * 8) * 2;
                int srco = row * HID + v * 8;
                *(uint4*)(smem + SM_W1HI + dsto) = *(const uint4*)(s1h + srco);
                *(uint4*)(smem + SM_W1LO + dsto) = *(const uint4*)(s1l + srco);
            }
            const unsigned short* s2h = w2hB + c * 64 * D;
            const unsigned short* s2l = w2lB + c * 64 * D;
            #pragma unroll 2
            for (int idx = tid; idx < 640; idx += 256) {
                int row = idx / 10, v = idx - row * 10;
                int dsto = (row * W2S + v * 8) * 2;
                int srco = row * D + v * 8;
                *(uint4*)(smem + SM_W2HI + dsto) = *(const uint4*)(s2h + srco);
                *(uint4*)(smem + SM_W2LO + dsto) = *(const uint4*)(s2l + srco);
            }
            if (tid < 64) sb1[tid] = b1[e * HID + c * 64 + tid];
        }
        __syncthreads();

        // ---- GEMM1: acc = X(64x80) @ W1chunk(80x64), 3-term split ----
        float acc[4][4];
        #pragma unroll
        for (int na = 0; na < 4; na++)
            #pragma unroll
            for (int i = 0; i < 4; i++) acc[na][i] = 0.f;

        #pragma unroll
        for (int ks = 0; ks < 5; ks++) {
            uint32_t ah[4], al[4];
            ldsm4(ah, aX + ks * 32);
            ldsm4(al, aX + ks * 32 + dXlo);
            #pragma unroll
            for (int na = 0; na < 4; na++) {
                uint32_t ba = bW1 + (ks * 16 * W1S + na * 8) * 2;
                uint32_t bh[2], bl[2];
                ldsm2t(bh, ba);
                ldsm2t(bl, ba + dW1lo);
                mma_bf16(acc[na], ah, bh);
                mma_bf16(acc[na], ah, bl);
                mma_bf16(acc[na], al, bh);
            }
        }

        // ---- epilogue: H = relu(acc + b1), split to bf16 hi/lo ----
        {
            int row0 = m_base + (lane >> 2);
            #pragma unroll
            for (int na = 0; na < 4; na++) {
                int col = warp_n * 32 + na * 8 + (lane & 3) * 2;
                float bb0 = sb1[col], bb1 = sb1[col + 1];
                float f0 = fmaxf(acc[na][0] + bb0, 0.f);
                float f1 = fmaxf(acc[na][1] + bb1, 0.f);
                float f2 = fmaxf(acc[na][2] + bb0, 0.f);
                float f3 = fmaxf(acc[na][3] + bb1, 0.f);
                __nv_bfloat162 h01 = __floats2bfloat162_rn(f0, f1);
                float2 hf01 = __bfloat1622float2(h01);
                __nv_bfloat162 l01 = __floats2bfloat162_rn(f0 - hf01.x, f1 - hf01.y);
                __nv_bfloat162 h23 = __floats2bfloat162_rn(f2, f3);
                float2 hf23 = __bfloat1622float2(h23);
                __nv_bfloat162 l23 = __floats2bfloat162_rn(f2 - hf23.x, f3 - hf23.y);
                int o0 = (row0 * HS + col) * 2;
                int o1 = ((row0 + 8) * HS + col) * 2;
                *(uint32_t*)(smem + SM_HHI + o0) = *(uint32_t*)&h01;
                *(uint32_t*)(smem + SM_HLO + o0) = *(uint32_t*)&l01;
                *(uint32_t*)(smem + SM_HHI + o1) = *(uint32_t*)&h23;
                *(uint32_t*)(smem + SM_HLO + o1) = *(uint32_t*)&l23;
            }
        }
        __syncthreads();

        // ---- GEMM2: yacc += H(64x64) @ W2chunk(64x80), 3-term split ----
        #pragma unroll
        for (int ks = 0; ks < 4; ks++) {
            uint32_t ah[4], al[4];
            ldsm4(ah, aH + ks * 32);
            ldsm4(al, aH + ks * 32 + dHlo);
            #pragma unroll
            for (int na = 0; na < 5; na++) {
                uint32_t ba = bW2 + (ks * 16 * W2S + na * 8) * 2;
                uint32_t bh[2], bl[2];
                ldsm2t(bh, ba);
                ldsm2t(bl, ba + dW2lo);
                mma_bf16(yacc[na], ah, bh);
                mma_bf16(yacc[na], ah, bl);
                mma_bf16(yacc[na], al, bh);
            }
        }
    }

    // ---- scatter: out[tok] += w * (y + b2)  (2 contributions/token) ----
    {
        int row0 = m_base + (lane >> 2);
        int tk0 = stok[row0], tk1 = stok[row0 + 8];
        float w0 = swt[row0], w1v = swt[row0 + 8];
        float* o0 = out + (size_t)(tk0 < 0 ? 0 : tk0) * D;
        float* o1 = out + (size_t)(tk1 < 0 ? 0 : tk1) * D;
        #pragma unroll
        for (int na = 0; na < 5; na++) {
            int col = warp_n * 40 + na * 8 + (lane & 3) * 2;
            float b20 = sb2[col], b21 = sb2[col + 1];
            if (tk0 >= 0) {
                atomicAdd(&o0[col],     w0 * (yacc[na][0] + b20));
                atomicAdd(&o0[col + 1], w0 * (yacc[na][1] + b21));
            }
            if (tk1 >= 0) {
                atomicAdd(&o1[col],     w1v * (yacc[na][2] + b20));
                atomicAdd(&o1[col + 1], w1v * (yacc[na][3] + b21));
            }
        }
    }
}

// ---------------------------------------------------------------------------
extern "C" void kernel_launch(void* const* d_in, const int* in_sizes, int n_in,
                              void* d_out, int out_size) {
    const float* x  = (const float*)d_in[0];
    const float* Wg = (const float*)d_in[1];
    const float* bg = (const float*)d_in[2];
    const float* W1 = (const float*)d_in[3];
    const float* b1 = (const float*)d_in[4];
    const float* W2 = (const float*)d_in[5];
    const float* b2 = (const float*)d_in[6];
    float* out = (float*)d_out;

    int T = in_sizes[0] / D;

    cudaFuncSetAttribute(ffn_kernel, cudaFuncAttributeMaxDynamicSharedMemorySize, SMEM_TOTAL);

    void *cntp, *bufAp, *bufBp;
    cudaGetSymbolAddress(&cntp,  g_cnt);
    cudaGetSymbolAddress(&bufAp, g_bufA);
    cudaGetSymbolAddress(&bufBp, g_bufB);
    float* bufA = (float*)bufAp;
    float* bufB = (float*)bufBp;

    const int NPREP = E * D * HID + E * HID * D;   // 409600
    prep_kernel<<<(NPREP + 255) / 256, 256>>>(W1, W2);

    int  rb     = (T + 255) / 256;
    int  chunks = (T + TBK - 1) / TBK;
    dim3 fgrid(chunks, E);

    const float* lin = x;
    for (int l = 0; l < NL; l++) {
        float* lout = (l == NL - 1) ? out : ((l & 1) ? bufB : bufA);
        cudaMemsetAsync(cntp, 0, sizeof(int) * E);
        cudaMemsetAsync(lout, 0, (size_t)T * D * sizeof(float));
        router_kernel<<<rb, 256>>>(lin, Wg + (size_t)l * D * E, bg + l * E, T);
        ffn_kernel<<<fgrid, 256, SMEM_TOTAL>>>(lin, lout, b1, b2);
        lin = lout;
    }
}

// round 5
// speedup vs baseline: 2.4719x; 1.0785x over previous
#include <cuda_runtime.h>
#include <cuda_bf16.h>
#include <math.h>
#include <stdint.h>

// Problem constants
#define D    80
#define E    8
#define HID  320
#define NL   4
#define TBK  64            // tokens per ffn block
#define NCK  5             // HID chunks of 64
#define MAXT 131072
#define RTB  128           // router tokens per block

// smem row strides (elements) — odd multiples of 8 -> conflict-free ldmatrix
#define XS   88
#define W1S  72
#define HS   72
#define W2S  88

// smem layout (bytes)
#define SM_STOK 0
#define SM_SWT  256
#define SM_SB1  512
#define SM_SB2  768
#define SM_XHI  1280
#define SM_XLO  (SM_XHI  + TBK * XS * 2)     // 12544
#define SM_W1HI (SM_XLO  + TBK * XS * 2)     // 23808
#define SM_W1LO (SM_W1HI + 80 * W1S * 2)     // 35328
#define SM_W2HI (SM_W1LO + 80 * W1S * 2)     // 46848
#define SM_W2LO (SM_W2HI + 64 * W2S * 2)     // 58112
#define SM_HHI  (SM_W2LO + 64 * W2S * 2)     // 69376
#define SM_HLO  (SM_HHI  + TBK * HS * 2)     // 78592
#define SMEM_TOTAL (SM_HLO + TBK * HS * 2)   // 87808

// ---------------------------------------------------------------------------
// Scratch (no cudaMalloc allowed)
// ---------------------------------------------------------------------------
__device__ float g_bufA[MAXT * D];
__device__ float g_bufB[MAXT * D];
__device__ int   g_cnt[E];
__device__ int   g_tok[E * MAXT];
__device__ float g_wt [E * MAXT];
// split-bf16 weights, natural layouts
__device__ __align__(16) unsigned short g_w1h[E * D * HID];   // [e][d][h]
__device__ __align__(16) unsigned short g_w1l[E * D * HID];
__device__ __align__(16) unsigned short g_w2h[E * HID * D];   // [e][h][d]
__device__ __align__(16) unsigned short g_w2l[E * HID * D];

// ---------------------------------------------------------------------------
// PTX helpers (sm_80-era: valid on compute_100 without the 'a' suffix)
// ---------------------------------------------------------------------------
__device__ __forceinline__ uint32_t smem_u32(const void* p) {
    uint32_t a;
    asm("{ .reg .u64 t; cvta.to.shared.u64 t, %1; cvt.u32.u64 %0, t; }" : "=r"(a) : "l"(p));
    return a;
}
__device__ __forceinline__ void ldsm4(uint32_t* r, uint32_t a) {
    asm volatile("ldmatrix.sync.aligned.m8n8.x4.shared.b16 {%0,%1,%2,%3}, [%4];"
        : "=r"(r[0]), "=r"(r[1]), "=r"(r[2]), "=r"(r[3]) : "r"(a));
}
__device__ __forceinline__ void ldsm4t(uint32_t* r, uint32_t a) {
    asm volatile("ldmatrix.sync.aligned.m8n8.x4.trans.shared.b16 {%0,%1,%2,%3}, [%4];"
        : "=r"(r[0]), "=r"(r[1]), "=r"(r[2]), "=r"(r[3]) : "r"(a));
}
__device__ __forceinline__ void ldsm2t(uint32_t* r, uint32_t a) {
    asm volatile("ldmatrix.sync.aligned.m8n8.x2.trans.shared.b16 {%0,%1}, [%2];"
        : "=r"(r[0]), "=r"(r[1]) : "r"(a));
}
__device__ __forceinline__ void mma_bf16(float* c, const uint32_t* a, const uint32_t* b) {
    asm volatile("mma.sync.aligned.m16n8k16.row.col.f32.bf16.bf16.f32 "
        "{%0,%1,%2,%3}, {%4,%5,%6,%7}, {%8,%9}, {%0,%1,%2,%3};"
        : "+f"(c[0]), "+f"(c[1]), "+f"(c[2]), "+f"(c[3])
        : "r"(a[0]), "r"(a[1]), "r"(a[2]), "r"(a[3]), "r"(b[0]), "r"(b[1]));
}

// ---------------------------------------------------------------------------
// Weight prep: elementwise split fp32 -> bf16 hi + lo
// ---------------------------------------------------------------------------
__global__ void prep_kernel(const float* __restrict__ W1, const float* __restrict__ W2) {
    int i = blockIdx.x * blockDim.x + threadIdx.x;
    const int N1 = E * D * HID;
    const int N2 = E * HID * D;
    if (i < N1) {
        float v = W1[i];
        __nv_bfloat16 h = __float2bfloat16(v);
        __nv_bfloat16 l = __float2bfloat16(v - __bfloat162float(h));
        g_w1h[i] = *(unsigned short*)&h;
        g_w1l[i] = *(unsigned short*)&l;
    } else if (i < N1 + N2) {
        int j = i - N1;
        float v = W2[j];
        __nv_bfloat16 h = __float2bfloat16(v);
        __nv_bfloat16 l = __float2bfloat16(v - __bfloat162float(h));
        g_w2h[j] = *(unsigned short*)&h;
        g_w2l[j] = *(unsigned short*)&l;
    }
}

// ---------------------------------------------------------------------------
// Router: coalesced smem staging, one token/thread compute, fused lout zeroing.
// Exact jax top_k tie semantics (strict > keeps lower index); raw logits = weights.
// ---------------------------------------------------------------------------
__global__ void __launch_bounds__(RTB)
router_kernel(const float* __restrict__ x,
              const float* __restrict__ Wg,
              const float* __restrict__ bg,
              float* __restrict__ lout, int T) {
    __shared__ float wg[D * E];
    __shared__ float bgs[E];
    __shared__ float xs[RTB * 81];

    int tid  = threadIdx.x;
    int base = blockIdx.x * RTB;
    int ntok = T - base; if (ntok > RTB) ntok = RTB;

    for (int i = tid; i < D * E; i += RTB) wg[i] = Wg[i];
    if (tid < E) bgs[tid] = bg[tid];

    // stage X (coalesced float4) + zero this block's slice of lout
    {
        const float4* gx = (const float4*)(x + (size_t)base * D);
        float4*       gz = (float4*)(lout + (size_t)base * D);
        int n4 = ntok * (D / 4);
        const float4 z = make_float4(0.f, 0.f, 0.f, 0.f);
        for (int i = tid; i < n4; i += RTB) {
            float4 v = gx[i];
            gz[i] = z;
            int r = i / 20, c = (i - r * 20) * 4;
            float* dst = &xs[r * 81 + c];
            dst[0] = v.x; dst[1] = v.y; dst[2] = v.z; dst[3] = v.w;
        }
    }
    __syncthreads();

    if (tid >= ntok) return;
    int t = base + tid;

    float acc[E];
    #pragma unroll
    for (int e = 0; e < E; e++) acc[e] = bgs[e];
    const float* xr = &xs[tid * 81];
    #pragma unroll 4
    for (int k = 0; k < D; k++) {
        float xv = xr[k];
        #pragma unroll
        for (int e = 0; e < E; e++) acc[e] = fmaf(xv, wg[k * E + e], acc[e]);
    }
    float v0 = -INFINITY, v1 = -INFINITY; int i0 = 0, i1 = 0;
    #pragma unroll
    for (int e = 0; e < E; e++) {
        float v = acc[e];
        if (v > v0)      { v1 = v0; i1 = i0; v0 = v; i0 = e; }
        else if (v > v1) { v1 = v;  i1 = e; }
    }
    int p0 = atomicAdd(&g_cnt[i0], 1);
    g_tok[i0 * MAXT + p0] = t;  g_wt[i0 * MAXT + p0] = v0;
    int p1 = atomicAdd(&g_cnt[i1], 1);
    g_tok[i1 * MAXT + p1] = t;  g_wt[i1 * MAXT + p1] = v1;
}

// ---------------------------------------------------------------------------
// FFN: 64 tokens of one expert; split-bf16 tensor-core GEMMs via mma.sync.
// B operands loaded with ldmatrix.x4.trans (16x16 per instruction).
// ---------------------------------------------------------------------------
__global__ void __launch_bounds__(256, 2)
ffn_kernel(const float* __restrict__ in,  float* __restrict__ out,
           const float* __restrict__ b1,  const float* __restrict__ b2) {
    extern __shared__ char smem[];
    uint32_t sb = smem_u32(smem);
    int tid  = threadIdx.x;
    int lane = tid & 31;
    int wid  = tid >> 5;

    int e = blockIdx.y;
    int n = g_cnt[e];
    int start = blockIdx.x * TBK;
    if (start >= n) return;

    int*   stok = (int*)  (smem + SM_STOK);
    float* swt  = (float*)(smem + SM_SWT);
    float* sb1  = (float*)(smem + SM_SB1);
    float* sb2  = (float*)(smem + SM_SB2);

    if (tid < TBK) {
        int p = start + tid;
        if (p < n) { stok[tid] = g_tok[e * MAXT + p]; swt[tid] = g_wt[e * MAXT + p]; }
        else       { stok[tid] = -1; swt[tid] = 0.f; }
    }
    if (tid < D) sb2[tid] = b2[e * D + tid];
    __syncthreads();

    // ---- gather X, split into bf16 hi/lo smem (2 threads per token) ----
    if (tid < 2 * TBK) {
        int r = tid >> 1, half = tid & 1;
        int tk = stok[r];
        const float* xr = in + (size_t)(tk < 0 ? 0 : tk) * D + half * 40;
        char* dh = smem + SM_XHI + (r * XS + half * 40) * 2;
        char* dl = smem + SM_XLO + (r * XS + half * 40) * 2;
        #pragma unroll
        for (int j = 0; j < 20; j++) {
            float2 v = (tk >= 0) ? *(const float2*)&xr[2 * j] : make_float2(0.f, 0.f);
            __nv_bfloat162 h2 = __floats2bfloat162_rn(v.x, v.y);
            float2 hf = __bfloat1622float2(h2);
            __nv_bfloat162 l2 = __floats2bfloat162_rn(v.x - hf.x, v.y - hf.y);
            *(uint32_t*)(dh + 4 * j) = *(uint32_t*)&h2;
            *(uint32_t*)(dl + 4 * j) = *(uint32_t*)&l2;
        }
    }

    // warp tiling: 4 (M) x 2 (N)
    int warp_m = wid >> 1;
    int warp_n = wid & 1;
    int m_base = warp_m * 16;

    // per-thread ldmatrix base addresses
    uint32_t aX   = sb + SM_XHI  + ((m_base + (lane & 15)) * XS + (lane >> 4) * 8) * 2;
    uint32_t aH   = sb + SM_HHI  + ((m_base + (lane & 15)) * HS + (lane >> 4) * 8) * 2;
    uint32_t bW1_4 = sb + SM_W1HI + ((lane & 15) * W1S + warp_n * 32 + (lane >> 4) * 8) * 2;
    uint32_t bW2_4 = sb + SM_W2HI + ((lane & 15) * W2S + warp_n * 40 + (lane >> 4) * 8) * 2;
    uint32_t bW2_2 = sb + SM_W2HI + ((lane & 15) * W2S + warp_n * 40 + 32) * 2;
    const int dXlo  = SM_XLO  - SM_XHI;
    const int dW1lo = SM_W1LO - SM_W1HI;
    const int dHlo  = SM_HLO  - SM_HHI;
    const int dW2lo = SM_W2LO - SM_W2HI;

    // GEMM2 accumulators persist over chunks: warp tile 16 x 40 (5 n-atoms)
    float yacc[5][4];
    #pragma unroll
    for (int na = 0; na < 5; na++)
        #pragma unroll
        for (int i = 0; i < 4; i++) yacc[na][i] = 0.f;

    const unsigned short* w1hB = g_w1h + e * D * HID;
    const unsigned short* w1lB = g_w1l + e * D * HID;
    const unsigned short* w2hB = g_w2h + e * HID * D;
    const unsigned short* w2lB = g_w2l + e * HID * D;

    for (int c = 0; c < NCK; c++) {
        __syncthreads();   // prev GEMM2 done with W2/H; X gather done (c=0)

        // ---- stage weight tiles into smem (vectorized, L2-hot) ----
        {
            const unsigned short* s1h = w1hB + c * 64;
            const unsigned short* s1l = w1lB + c * 64;
            #pragma unroll 2
            for (int idx = tid; idx < 640; idx += 256) {
                int row = idx >> 3, v = idx & 7;
                int dsto = (row * W1S + v * 8) * 2;
                int srco = row * HID + v * 8;
                *(uint4*)(smem + SM_W1HI + dsto) = *(const uint4*)(s1h + srco);
                *(uint4*)(smem + SM_W1LO + dsto) = *(const uint4*)(s1l + srco);
            }
            const unsigned short* s2h = w2hB + c * 64 * D;
            const unsigned short* s2l = w2lB + c * 64 * D;
            #pragma unroll 2
            for (int idx = tid; idx < 640; idx += 256) {
                int row = idx / 10, v = idx - row * 10;
                int dsto = (row * W2S + v * 8) * 2;
                int srco = row * D + v * 8;
                *(uint4*)(smem + SM_W2HI + dsto) = *(const uint4*)(s2h + srco);
                *(uint4*)(smem + SM_W2LO + dsto) = *(const uint4*)(s2l + srco);
            }
            if (tid < 64) sb1[tid] = b1[e * HID + c * 64 + tid];
        }
        __syncthreads();

        // ---- GEMM1: acc = X(64x80) @ W1chunk(80x64), 3-term split ----
        float acc[4][4];
        #pragma unroll
        for (int na = 0; na < 4; na++)
            #pragma unroll
            for (int i = 0; i < 4; i++) acc[na][i] = 0.f;

        #pragma unroll
        for (int ks = 0; ks < 5; ks++) {
            uint32_t ah[4], al[4];
            ldsm4(ah, aX + ks * 32);
            ldsm4(al, aX + ks * 32 + dXlo);
            #pragma unroll
            for (int np = 0; np < 2; np++) {
                uint32_t ba = bW1_4 + (ks * 16 * W1S + np * 16) * 2;
                uint32_t bh[4], bl[4];
                ldsm4t(bh, ba);
                ldsm4t(bl, ba + dW1lo);
                mma_bf16(acc[2 * np],     ah, bh);
                mma_bf16(acc[2 * np],     ah, bl);
                mma_bf16(acc[2 * np],     al, bh);
                mma_bf16(acc[2 * np + 1], ah, bh + 2);
                mma_bf16(acc[2 * np + 1], ah, bl + 2);
                mma_bf16(acc[2 * np + 1], al, bh + 2);
            }
        }

        // ---- epilogue: H = relu(acc + b1), split to bf16 hi/lo ----
        {
            int row0 = m_base + (lane >> 2);
            #pragma unroll
            for (int na = 0; na < 4; na++) {
                int col = warp_n * 32 + na * 8 + (lane & 3) * 2;
                float bb0 = sb1[col], bb1 = sb1[col + 1];
                float f0 = fmaxf(acc[na][0] + bb0, 0.f);
                float f1 = fmaxf(acc[na][1] + bb1, 0.f);
                float f2 = fmaxf(acc[na][2] + bb0, 0.f);
                float f3 = fmaxf(acc[na][3] + bb1, 0.f);
                __nv_bfloat162 h01 = __floats2bfloat162_rn(f0, f1);
                float2 hf01 = __bfloat1622float2(h01);
                __nv_bfloat162 l01 = __floats2bfloat162_rn(f0 - hf01.x, f1 - hf01.y);
                __nv_bfloat162 h23 = __floats2bfloat162_rn(f2, f3);
                float2 hf23 = __bfloat1622float2(h23);
                __nv_bfloat162 l23 = __floats2bfloat162_rn(f2 - hf23.x, f3 - hf23.y);
                int o0 = (row0 * HS + col) * 2;
                int o1 = ((row0 + 8) * HS + col) * 2;
                *(uint32_t*)(smem + SM_HHI + o0) = *(uint32_t*)&h01;
                *(uint32_t*)(smem + SM_HLO + o0) = *(uint32_t*)&l01;
                *(uint32_t*)(smem + SM_HHI + o1) = *(uint32_t*)&h23;
                *(uint32_t*)(smem + SM_HLO + o1) = *(uint32_t*)&l23;
            }
        }
        __syncthreads();

        // ---- GEMM2: yacc += H(64x64) @ W2chunk(64x80), 3-term split ----
        #pragma unroll
        for (int ks = 0; ks < 4; ks++) {
            uint32_t ah[4], al[4];
            ldsm4(ah, aH + ks * 32);
            ldsm4(al, aH + ks * 32 + dHlo);
            #pragma unroll
            for (int np = 0; np < 2; np++) {
                uint32_t ba = bW2_4 + (ks * 16 * W2S + np * 16) * 2;
                uint32_t bh[4], bl[4];
                ldsm4t(bh, ba);
                ldsm4t(bl, ba + dW2lo);
                mma_bf16(yacc[2 * np],     ah, bh);
                mma_bf16(yacc[2 * np],     ah, bl);
                mma_bf16(yacc[2 * np],     al, bh);
                mma_bf16(yacc[2 * np + 1], ah, bh + 2);
                mma_bf16(yacc[2 * np + 1], ah, bl + 2);
                mma_bf16(yacc[2 * np + 1], al, bh + 2);
            }
            {
                uint32_t ba = bW2_2 + (ks * 16 * W2S) * 2;
                uint32_t bh[2], bl[2];
                ldsm2t(bh, ba);
                ldsm2t(bl, ba + dW2lo);
                mma_bf16(yacc[4], ah, bh);
                mma_bf16(yacc[4], ah, bl);
                mma_bf16(yacc[4], al, bh);
            }
        }
    }

    // ---- scatter: out[tok] += w * (y + b2)  (2 contributions/token) ----
    {
        int row0 = m_base + (lane >> 2);
        int tk0 = stok[row0], tk1 = stok[row0 + 8];
        float w0 = swt[row0], w1v = swt[row0 + 8];
        float* o0 = out + (size_t)(tk0 < 0 ? 0 : tk0) * D;
        float* o1 = out + (size_t)(tk1 < 0 ? 0 : tk1) * D;
        #pragma unroll
        for (int na = 0; na < 5; na++) {
            int col = warp_n * 40 + na * 8 + (lane & 3) * 2;
            float b20 = sb2[col], b21 = sb2[col + 1];
            if (tk0 >= 0) {
                atomicAdd(&o0[col],     w0 * (yacc[na][0] + b20));
                atomicAdd(&o0[col + 1], w0 * (yacc[na][1] + b21));
            }
            if (tk1 >= 0) {
                atomicAdd(&o1[col],     w1v * (yacc[na][2] + b20));
                atomicAdd(&o1[col + 1], w1v * (yacc[na][3] + b21));
            }
        }
    }
}

// ---------------------------------------------------------------------------
extern "C" void kernel_launch(void* const* d_in, const int* in_sizes, int n_in,
                              void* d_out, int out_size) {
    const float* x  = (const float*)d_in[0];
    const float* Wg = (const float*)d_in[1];
    const float* bg = (const float*)d_in[2];
    const float* W1 = (const float*)d_in[3];
    const float* b1 = (const float*)d_in[4];
    const float* W2 = (const float*)d_in[5];
    const float* b2 = (const float*)d_in[6];
    float* out = (float*)d_out;

    int T = in_sizes[0] / D;

    cudaFuncSetAttribute(ffn_kernel, cudaFuncAttributeMaxDynamicSharedMemorySize, SMEM_TOTAL);

    void *cntp, *bufAp, *bufBp;
    cudaGetSymbolAddress(&cntp,  g_cnt);
    cudaGetSymbolAddress(&bufAp, g_bufA);
    cudaGetSymbolAddress(&bufBp, g_bufB);
    float* bufA = (float*)bufAp;
    float* bufB = (float*)bufBp;

    const int NPREP = E * D * HID + E * HID * D;   // 409600
    prep_kernel<<<(NPREP + 255) / 256, 256>>>(W1, W2);

    int  rb     = (T + RTB - 1) / RTB;
    int  chunks = (T + TBK - 1) / TBK;
    dim3 fgrid(chunks, E);

    const float* lin = x;
    for (int l = 0; l < NL; l++) {
        float* lout = (l == NL - 1) ? out : ((l & 1) ? bufB : bufA);
        cudaMemsetAsync(cntp, 0, sizeof(int) * E);
        // router zeroes lout and builds expert lists
        router_kernel<<<rb, RTB>>>(lin, Wg + (size_t)l * D * E, bg + l * E, lout, T);
        ffn_kernel<<<fgrid, 256, SMEM_TOTAL>>>(lin, lout, b1, b2);
        lin = lout;
    }
}